// round 1
// baseline (speedup 1.0000x reference)
#include <cuda_runtime.h>

#define NH   12
#define TSEQ 4096
#define BATCH 2
#define CED  768

// Scratch buffers (no cudaMalloc allowed): qkv = [B,T,3C], att = [B,T,C]
__device__ float g_qkv[(size_t)BATCH * TSEQ * 3 * CED];
__device__ float g_att[(size_t)BATCH * TSEQ * CED];

// ---------------------------------------------------------------------------
// SGEMM: C[M,N] = A[M,K] @ B[K,N] + bias[N], all row-major fp32.
// BM=BN=128, BK=8, 256 threads, 8x8 per thread (split 4+4 frags, conflict-free).
// Requires M%128==0, N%128==0, K%8==0 (true for all three GEMMs here).
// ---------------------------------------------------------------------------
__global__ __launch_bounds__(256) void sgemm_bias_kernel(
    const float* __restrict__ A, const float* __restrict__ B,
    const float* __restrict__ bias, float* __restrict__ C,
    int M, int N, int K)
{
    __shared__ float As[8][128];
    __shared__ float Bs[8][128];

    const int tid = threadIdx.x;
    const int tx = tid & 15;
    const int ty = tid >> 4;
    const int rowBase = blockIdx.y * 128;
    const int colBase = blockIdx.x * 128;

    float acc[8][8];
#pragma unroll
    for (int i = 0; i < 8; i++)
#pragma unroll
        for (int j = 0; j < 8; j++) acc[i][j] = 0.f;

    const int aRow = tid >> 1;        // 0..127
    const int aCol = (tid & 1) * 4;   // 0 or 4
    const int bRow = tid >> 5;        // 0..7
    const int bCol = (tid & 31) * 4;  // 0..124

    const float* Ap = A + (size_t)(rowBase + aRow) * K + aCol;
    const float* Bp = B + (size_t)bRow * N + colBase + bCol;

    for (int k0 = 0; k0 < K; k0 += 8) {
        float4 av = *(const float4*)(Ap + k0);
        float4 bv = *(const float4*)(Bp + (size_t)k0 * N);
        As[aCol + 0][aRow] = av.x;
        As[aCol + 1][aRow] = av.y;
        As[aCol + 2][aRow] = av.z;
        As[aCol + 3][aRow] = av.w;
        *(float4*)&Bs[bRow][bCol] = bv;
        __syncthreads();
#pragma unroll
        for (int kk = 0; kk < 8; kk++) {
            float a[8], b[8];
            *(float4*)&a[0] = *(const float4*)&As[kk][ty * 4];
            *(float4*)&a[4] = *(const float4*)&As[kk][ty * 4 + 64];
            *(float4*)&b[0] = *(const float4*)&Bs[kk][tx * 4];
            *(float4*)&b[4] = *(const float4*)&Bs[kk][tx * 4 + 64];
#pragma unroll
            for (int i = 0; i < 8; i++)
#pragma unroll
                for (int j = 0; j < 8; j++)
                    acc[i][j] = fmaf(a[i], b[j], acc[i][j]);
        }
        __syncthreads();
    }

#pragma unroll
    for (int ii = 0; ii < 2; ii++) {
#pragma unroll
        for (int i = 0; i < 4; i++) {
            const int r = rowBase + ii * 64 + ty * 4 + i;
#pragma unroll
            for (int jj = 0; jj < 2; jj++) {
                const int c = colBase + jj * 64 + tx * 4;
                float4 bsv = *(const float4*)&bias[c];
                float4 o;
                o.x = acc[ii * 4 + i][jj * 4 + 0] + bsv.x;
                o.y = acc[ii * 4 + i][jj * 4 + 1] + bsv.y;
                o.z = acc[ii * 4 + i][jj * 4 + 2] + bsv.z;
                o.w = acc[ii * 4 + i][jj * 4 + 3] + bsv.w;
                *(float4*)&C[(size_t)r * N + c] = o;
            }
        }
    }
}

// ---------------------------------------------------------------------------
// Flash attention, fp32, causal. qkv layout per row t (stride 2304 floats):
//   cols [0,768) = K, [768,1536) = Q, [1536,2304) = V   (reference order k,q,v!)
// Block tile: 128 q-rows x 64 k-cols, D=64. 256 threads: thread (ty=tid/16,
// tx=tid%16) owns S rows ty*8..+7, cols tx*4..+3; O rows same, d-cols tx*4..+3.
// All operand smem tiles stored d-major (kk-major) for vectorized LDS.128.
// ---------------------------------------------------------------------------
#define QSTRIDE 132   // 128 q + pad (keeps float4 alignment, breaks bank cycles)
#define KSTRIDE 68    // 64 k + pad

__global__ __launch_bounds__(256) void attn_kernel(
    const float* __restrict__ qkv, float* __restrict__ att)
{
    extern __shared__ float sm[];
    float* Qts = sm;                       // [64 d][QSTRIDE]  (Q^T, pre-scaled)
    float* Kts = Qts + 64 * QSTRIDE;       // [64 d][KSTRIDE]  (K^T)
    float* Vs  = Kts + 64 * KSTRIDE;       // [64 k][64 d]     (natural)
    float* Pts = Vs + 64 * 64;             // [64 k][QSTRIDE]  (P^T)

    const int tid = threadIdx.x;
    const int tx = tid & 15;
    const int ty = tid >> 4;
    const int qb = blockIdx.x;
    const int b  = blockIdx.y / NH;
    const int h  = blockIdx.y % NH;
    const int q0 = qb * 128;

    const size_t rowstr = 3 * CED;  // 2304
    const float* qbase = qkv + (size_t)(b * TSEQ + q0) * rowstr + CED + h * 64;
    const float* kbase = qkv + (size_t)(b * TSEQ) * rowstr + h * 64;
    const float* vbase = qkv + (size_t)(b * TSEQ) * rowstr + 2 * CED + h * 64;

    // Load Q tile [128 x 64] transposed into Qts[d][q], pre-scaled by 1/sqrt(64)
    for (int idx = tid; idx < 128 * 16; idx += 256) {
        const int row = idx >> 4;
        const int c = (idx & 15) * 4;
        float4 v = *(const float4*)(qbase + (size_t)row * rowstr + c);
        Qts[(c + 0) * QSTRIDE + row] = v.x * 0.125f;
        Qts[(c + 1) * QSTRIDE + row] = v.y * 0.125f;
        Qts[(c + 2) * QSTRIDE + row] = v.z * 0.125f;
        Qts[(c + 3) * QSTRIDE + row] = v.w * 0.125f;
    }

    float m[8], l[8], o[8][4];
#pragma unroll
    for (int i = 0; i < 8; i++) {
        m[i] = -1e30f;
        l[i] = 0.f;
#pragma unroll
        for (int j = 0; j < 4; j++) o[i][j] = 0.f;
    }

    const int ntiles = 2 * qb + 2;  // causal: k up to q0+127
    for (int kt = 0; kt < ntiles; kt++) {
        __syncthreads();  // protect Kts/Vs/Pts reuse
        const int krow0 = kt * 64;
        // Load K tile transposed into Kts[d][k], V tile naturally into Vs[k][d]
        for (int idx = tid; idx < 64 * 16; idx += 256) {
            const int row = idx >> 4;
            const int c = (idx & 15) * 4;
            float4 kv = *(const float4*)(kbase + (size_t)(krow0 + row) * rowstr + c);
            Kts[(c + 0) * KSTRIDE + row] = kv.x;
            Kts[(c + 1) * KSTRIDE + row] = kv.y;
            Kts[(c + 2) * KSTRIDE + row] = kv.z;
            Kts[(c + 3) * KSTRIDE + row] = kv.w;
            float4 vv = *(const float4*)(vbase + (size_t)(krow0 + row) * rowstr + c);
            *(float4*)&Vs[row * 64 + c] = vv;
        }
        __syncthreads();

        // S = (Q*scale) @ K^T   -> s[8][4]
        float s[8][4];
#pragma unroll
        for (int i = 0; i < 8; i++)
#pragma unroll
            for (int j = 0; j < 4; j++) s[i][j] = 0.f;

#pragma unroll 8
        for (int kk = 0; kk < 64; kk++) {
            float qa[8], kb[4];
            *(float4*)&qa[0] = *(const float4*)&Qts[kk * QSTRIDE + ty * 8];
            *(float4*)&qa[4] = *(const float4*)&Qts[kk * QSTRIDE + ty * 8 + 4];
            *(float4*)&kb[0] = *(const float4*)&Kts[kk * KSTRIDE + tx * 4];
#pragma unroll
            for (int i = 0; i < 8; i++)
#pragma unroll
                for (int j = 0; j < 4; j++)
                    s[i][j] = fmaf(qa[i], kb[j], s[i][j]);
        }

        // Causal mask only on the two diagonal-overlapping tiles
        if (kt >= 2 * qb) {
#pragma unroll
            for (int i = 0; i < 8; i++) {
                const int qg = q0 + ty * 8 + i;
#pragma unroll
                for (int j = 0; j < 4; j++) {
                    const int kg = krow0 + tx * 4 + j;
                    if (kg > qg) s[i][j] = -1e30f;
                }
            }
        }

        // Online softmax (row stats shared across the 16-lane tx-group)
#pragma unroll
        for (int i = 0; i < 8; i++) {
            float rm = fmaxf(fmaxf(s[i][0], s[i][1]), fmaxf(s[i][2], s[i][3]));
#pragma unroll
            for (int off = 1; off < 16; off <<= 1)
                rm = fmaxf(rm, __shfl_xor_sync(0xffffffffu, rm, off));
            const float mn = fmaxf(m[i], rm);
            const float sc = __expf(m[i] - mn);
            float rs = 0.f;
#pragma unroll
            for (int j = 0; j < 4; j++) {
                const float p = __expf(s[i][j] - mn);
                s[i][j] = p;
                rs += p;
            }
#pragma unroll
            for (int off = 1; off < 16; off <<= 1)
                rs += __shfl_xor_sync(0xffffffffu, rs, off);
            l[i] = l[i] * sc + rs;
            m[i] = mn;
#pragma unroll
            for (int j = 0; j < 4; j++) {
                o[i][j] *= sc;
                Pts[(tx * 4 + j) * QSTRIDE + ty * 8 + i] = s[i][j];
            }
        }
        __syncthreads();  // Pts visible to all

        // O += P @ V
#pragma unroll 8
        for (int kk = 0; kk < 64; kk++) {
            float pa[8], vb[4];
            *(float4*)&pa[0] = *(const float4*)&Pts[kk * QSTRIDE + ty * 8];
            *(float4*)&pa[4] = *(const float4*)&Pts[kk * QSTRIDE + ty * 8 + 4];
            *(float4*)&vb[0] = *(const float4*)&Vs[kk * 64 + tx * 4];
#pragma unroll
            for (int i = 0; i < 8; i++)
#pragma unroll
                for (int j = 0; j < 4; j++)
                    o[i][j] = fmaf(pa[i], vb[j], o[i][j]);
        }
    }

    // Normalize and write [B,T,C] with head interleave
#pragma unroll
    for (int i = 0; i < 8; i++) {
        const float inv = 1.0f / l[i];
        const size_t row = (size_t)(b * TSEQ + q0 + ty * 8 + i);
        float4 r;
        r.x = o[i][0] * inv;
        r.y = o[i][1] * inv;
        r.z = o[i][2] * inv;
        r.w = o[i][3] * inv;
        *(float4*)&att[row * CED + h * 64 + tx * 4] = r;
    }
}

// ---------------------------------------------------------------------------

extern "C" void kernel_launch(void* const* d_in, const int* in_sizes, int n_in,
                              void* d_out, int out_size)
{
    (void)in_sizes; (void)n_in; (void)out_size;
    const float* x      = (const float*)d_in[0];
    const float* W_attn = (const float*)d_in[1];
    const float* b_attn = (const float*)d_in[2];
    const float* W_proj = (const float*)d_in[3];
    const float* b_proj = (const float*)d_in[4];
    float* out = (float*)d_out;

    float* qkv = nullptr;
    float* attv = nullptr;
    cudaGetSymbolAddress((void**)&qkv, g_qkv);
    cudaGetSymbolAddress((void**)&attv, g_att);

    const int M = BATCH * TSEQ;   // 8192
    const int attn_smem = (64 * QSTRIDE + 64 * KSTRIDE + 64 * 64 + 64 * QSTRIDE) * 4;
    cudaFuncSetAttribute(attn_kernel, cudaFuncAttributeMaxDynamicSharedMemorySize,
                         attn_smem);

    // 1) qkv = x @ W_attn + b_attn          [8192, 2304]
    sgemm_bias_kernel<<<dim3(3 * CED / 128, M / 128), 256>>>(
        x, W_attn, b_attn, qkv, M, 3 * CED, CED);

    // 2) causal flash attention              [8192, 768]
    attn_kernel<<<dim3(TSEQ / 128, BATCH * NH), 256, attn_smem>>>(qkv, attv);

    // 3) out = att @ W_proj + b_proj         [8192, 768]
    sgemm_bias_kernel<<<dim3(CED / 128, M / 128), 256>>>(
        attv, W_proj, b_proj, out, M, CED, CED);
}

// round 2
// speedup vs baseline: 1.0160x; 1.0160x over previous
#include <cuda_runtime.h>

#define NH   12
#define TSEQ 4096
#define BATCH 2
#define CED  768

// Scratch buffers (no cudaMalloc allowed): qkv = [B,T,3C], att = [B,T,C]
__device__ float g_qkv[(size_t)BATCH * TSEQ * 3 * CED];
__device__ float g_att[(size_t)BATCH * TSEQ * CED];

// ---------------------------------------------------------------------------
// SGEMM: C[M,N] = A[M,K] @ B[K,N] + bias[N], all row-major fp32.
// BM=BN=128, BK=8, 256 threads, 8x8 per thread (split 4+4 frags, conflict-free).
// ---------------------------------------------------------------------------
__global__ __launch_bounds__(256) void sgemm_bias_kernel(
    const float* __restrict__ A, const float* __restrict__ B,
    const float* __restrict__ bias, float* __restrict__ C,
    int M, int N, int K)
{
    __shared__ float As[8][128];
    __shared__ float Bs[8][128];

    const int tid = threadIdx.x;
    const int tx = tid & 15;
    const int ty = tid >> 4;
    const int rowBase = blockIdx.y * 128;
    const int colBase = blockIdx.x * 128;

    float acc[8][8];
#pragma unroll
    for (int i = 0; i < 8; i++)
#pragma unroll
        for (int j = 0; j < 8; j++) acc[i][j] = 0.f;

    const int aRow = tid >> 1;        // 0..127
    const int aCol = (tid & 1) * 4;   // 0 or 4
    const int bRow = tid >> 5;        // 0..7
    const int bCol = (tid & 31) * 4;  // 0..124

    const float* Ap = A + (size_t)(rowBase + aRow) * K + aCol;
    const float* Bp = B + (size_t)bRow * N + colBase + bCol;

    for (int k0 = 0; k0 < K; k0 += 8) {
        float4 av = *(const float4*)(Ap + k0);
        float4 bv = *(const float4*)(Bp + (size_t)k0 * N);
        As[aCol + 0][aRow] = av.x;
        As[aCol + 1][aRow] = av.y;
        As[aCol + 2][aRow] = av.z;
        As[aCol + 3][aRow] = av.w;
        *(float4*)&Bs[bRow][bCol] = bv;
        __syncthreads();
#pragma unroll
        for (int kk = 0; kk < 8; kk++) {
            float a[8], b[8];
            *(float4*)&a[0] = *(const float4*)&As[kk][ty * 4];
            *(float4*)&a[4] = *(const float4*)&As[kk][ty * 4 + 64];
            *(float4*)&b[0] = *(const float4*)&Bs[kk][tx * 4];
            *(float4*)&b[4] = *(const float4*)&Bs[kk][tx * 4 + 64];
#pragma unroll
            for (int i = 0; i < 8; i++)
#pragma unroll
                for (int j = 0; j < 8; j++)
                    acc[i][j] = fmaf(a[i], b[j], acc[i][j]);
        }
        __syncthreads();
    }

#pragma unroll
    for (int ii = 0; ii < 2; ii++) {
#pragma unroll
        for (int i = 0; i < 4; i++) {
            const int r = rowBase + ii * 64 + ty * 4 + i;
#pragma unroll
            for (int jj = 0; jj < 2; jj++) {
                const int c = colBase + jj * 64 + tx * 4;
                float4 bsv = *(const float4*)&bias[c];
                float4 o;
                o.x = acc[ii * 4 + i][jj * 4 + 0] + bsv.x;
                o.y = acc[ii * 4 + i][jj * 4 + 1] + bsv.y;
                o.z = acc[ii * 4 + i][jj * 4 + 2] + bsv.z;
                o.w = acc[ii * 4 + i][jj * 4 + 3] + bsv.w;
                *(float4*)&C[(size_t)r * N + c] = o;
            }
        }
    }
}

// ---------------------------------------------------------------------------
// Flash attention, fp32, causal. qkv row layout (stride 2304 floats):
//   [0,768)=K, [768,1536)=Q, [1536,2304)=V   (reference splits k,q,v!)
// Tile: 128 q-rows x 64 k-cols, D=64. 256 threads, thread (ty,tx) owns
// S rows ty*8..+7 / cols tx*4..+3 and O rows same / d-cols tx*4..+3.
// KEY CHANGE R2: __launch_bounds__(256,2) + 99KB smem -> 2 CTAs/SM so one
// CTA's GEMM overlaps the other's softmax / syncs / tile loads.
// ---------------------------------------------------------------------------
#define QSTRIDE 132   // 128 q + pad
#define KSTRIDE 68    // 64 k + pad

__global__ __launch_bounds__(256, 2) void attn_kernel(
    const float* __restrict__ qkv, float* __restrict__ att)
{
    extern __shared__ float sm[];
    float* Qts = sm;                       // [64 d][QSTRIDE]  (Q^T, pre-scaled)
    float* Kts = Qts + 64 * QSTRIDE;       // [64 d][KSTRIDE]  (K^T)
    float* Vs  = Kts + 64 * KSTRIDE;       // [64 k][64 d]
    float* Pts = Vs + 64 * 64;             // [64 k][QSTRIDE]  (P^T)

    const int tid = threadIdx.x;
    const int tx = tid & 15;
    const int ty = tid >> 4;
    const int qb = blockIdx.x;
    const int b  = blockIdx.y / NH;
    const int h  = blockIdx.y % NH;
    const int q0 = qb * 128;

    const size_t rowstr = 3 * CED;  // 2304
    const float* qbase = qkv + (size_t)(b * TSEQ + q0) * rowstr + CED + h * 64;
    const float* kbase = qkv + (size_t)(b * TSEQ) * rowstr + h * 64;
    const float* vbase = qkv + (size_t)(b * TSEQ) * rowstr + 2 * CED + h * 64;

    // Load Q tile [128 x 64] transposed into Qts[d][q], pre-scaled by 1/8
    for (int idx = tid; idx < 128 * 16; idx += 256) {
        const int row = idx >> 4;
        const int c = (idx & 15) * 4;
        float4 v = *(const float4*)(qbase + (size_t)row * rowstr + c);
        Qts[(c + 0) * QSTRIDE + row] = v.x * 0.125f;
        Qts[(c + 1) * QSTRIDE + row] = v.y * 0.125f;
        Qts[(c + 2) * QSTRIDE + row] = v.z * 0.125f;
        Qts[(c + 3) * QSTRIDE + row] = v.w * 0.125f;
    }

    float m[8], l[8], o[8][4];
#pragma unroll
    for (int i = 0; i < 8; i++) {
        m[i] = -1e30f;
        l[i] = 0.f;
#pragma unroll
        for (int j = 0; j < 4; j++) o[i][j] = 0.f;
    }

    const int ntiles = 2 * qb + 2;  // causal: k up to q0+127
    for (int kt = 0; kt < ntiles; kt++) {
        __syncthreads();  // protect Kts/Vs/Pts reuse
        const int krow0 = kt * 64;
        for (int idx = tid; idx < 64 * 16; idx += 256) {
            const int row = idx >> 4;
            const int c = (idx & 15) * 4;
            float4 kv = *(const float4*)(kbase + (size_t)(krow0 + row) * rowstr + c);
            Kts[(c + 0) * KSTRIDE + row] = kv.x;
            Kts[(c + 1) * KSTRIDE + row] = kv.y;
            Kts[(c + 2) * KSTRIDE + row] = kv.z;
            Kts[(c + 3) * KSTRIDE + row] = kv.w;
            float4 vv = *(const float4*)(vbase + (size_t)(krow0 + row) * rowstr + c);
            *(float4*)&Vs[row * 64 + c] = vv;
        }
        __syncthreads();

        // S = (Q*scale) @ K^T
        float s[8][4];
#pragma unroll
        for (int i = 0; i < 8; i++)
#pragma unroll
            for (int j = 0; j < 4; j++) s[i][j] = 0.f;

#pragma unroll 8
        for (int kk = 0; kk < 64; kk++) {
            float qa[8], kb[4];
            *(float4*)&qa[0] = *(const float4*)&Qts[kk * QSTRIDE + ty * 8];
            *(float4*)&qa[4] = *(const float4*)&Qts[kk * QSTRIDE + ty * 8 + 4];
            *(float4*)&kb[0] = *(const float4*)&Kts[kk * KSTRIDE + tx * 4];
#pragma unroll
            for (int i = 0; i < 8; i++)
#pragma unroll
                for (int j = 0; j < 4; j++)
                    s[i][j] = fmaf(qa[i], kb[j], s[i][j]);
        }

        // Causal mask only on diagonal-overlapping tiles
        if (kt >= 2 * qb) {
#pragma unroll
            for (int i = 0; i < 8; i++) {
                const int qg = q0 + ty * 8 + i;
#pragma unroll
                for (int j = 0; j < 4; j++) {
                    const int kg = krow0 + tx * 4 + j;
                    if (kg > qg) s[i][j] = -1e30f;
                }
            }
        }

        // Online softmax (row stats across the 16-lane tx-group)
#pragma unroll
        for (int i = 0; i < 8; i++) {
            float rm = fmaxf(fmaxf(s[i][0], s[i][1]), fmaxf(s[i][2], s[i][3]));
#pragma unroll
            for (int off = 1; off < 16; off <<= 1)
                rm = fmaxf(rm, __shfl_xor_sync(0xffffffffu, rm, off));
            const float mn = fmaxf(m[i], rm);
            const float sc = __expf(m[i] - mn);
            float rs = 0.f;
#pragma unroll
            for (int j = 0; j < 4; j++) {
                const float p = __expf(s[i][j] - mn);
                s[i][j] = p;
                rs += p;
            }
#pragma unroll
            for (int off = 1; off < 16; off <<= 1)
                rs += __shfl_xor_sync(0xffffffffu, rs, off);
            l[i] = l[i] * sc + rs;
            m[i] = mn;
#pragma unroll
            for (int j = 0; j < 4; j++) {
                o[i][j] *= sc;
                Pts[(tx * 4 + j) * QSTRIDE + ty * 8 + i] = s[i][j];
            }
        }
        __syncthreads();

        // O += P @ V
#pragma unroll 8
        for (int kk = 0; kk < 64; kk++) {
            float pa[8], vb[4];
            *(float4*)&pa[0] = *(const float4*)&Pts[kk * QSTRIDE + ty * 8];
            *(float4*)&pa[4] = *(const float4*)&Pts[kk * QSTRIDE + ty * 8 + 4];
            *(float4*)&vb[0] = *(const float4*)&Vs[kk * 64 + tx * 4];
#pragma unroll
            for (int i = 0; i < 8; i++)
#pragma unroll
                for (int j = 0; j < 4; j++)
                    o[i][j] = fmaf(pa[i], vb[j], o[i][j]);
        }
    }

    // Normalize and write [B,T,C] with head interleave
#pragma unroll
    for (int i = 0; i < 8; i++) {
        const float inv = 1.0f / l[i];
        const size_t row = (size_t)(b * TSEQ + q0 + ty * 8 + i);
        float4 r;
        r.x = o[i][0] * inv;
        r.y = o[i][1] * inv;
        r.z = o[i][2] * inv;
        r.w = o[i][3] * inv;
        *(float4*)&att[row * CED + h * 64 + tx * 4] = r;
    }
}

// ---------------------------------------------------------------------------

extern "C" void kernel_launch(void* const* d_in, const int* in_sizes, int n_in,
                              void* d_out, int out_size)
{
    (void)in_sizes; (void)n_in; (void)out_size;
    const float* x      = (const float*)d_in[0];
    const float* W_attn = (const float*)d_in[1];
    const float* b_attn = (const float*)d_in[2];
    const float* W_proj = (const float*)d_in[3];
    const float* b_proj = (const float*)d_in[4];
    float* out = (float*)d_out;

    float* qkv = nullptr;
    float* attv = nullptr;
    cudaGetSymbolAddress((void**)&qkv, g_qkv);
    cudaGetSymbolAddress((void**)&attv, g_att);

    const int M = BATCH * TSEQ;   // 8192
    const int attn_smem = (64 * QSTRIDE + 64 * KSTRIDE + 64 * 64 + 64 * QSTRIDE) * 4;
    cudaFuncSetAttribute(attn_kernel, cudaFuncAttributeMaxDynamicSharedMemorySize,
                         attn_smem);

    // 1) qkv = x @ W_attn + b_attn          [8192, 2304]
    sgemm_bias_kernel<<<dim3(3 * CED / 128, M / 128), 256>>>(
        x, W_attn, b_attn, qkv, M, 3 * CED, CED);

    // 2) causal flash attention              [8192, 768]
    attn_kernel<<<dim3(TSEQ / 128, BATCH * NH), 256, attn_smem>>>(qkv, attv);

    // 3) out = att @ W_proj + b_proj         [8192, 768]
    sgemm_bias_kernel<<<dim3(CED / 128, M / 128), 256>>>(
        attv, W_proj, b_proj, out, M, CED, CED);
}

// round 3
// speedup vs baseline: 1.7689x; 1.7411x over previous
#include <cuda_runtime.h>
#include <cuda_bf16.h>
#include <cstdint>

#define NH   12
#define TSEQ 4096
#define BATCH 2
#define CED  768

// Scratch buffers (no cudaMalloc allowed): qkv = [B,T,3C], att = [B,T,C]
__device__ float g_qkv[(size_t)BATCH * TSEQ * 3 * CED];
__device__ float g_att[(size_t)BATCH * TSEQ * CED];

// ---------------------------------------------------------------------------
// SGEMM (unchanged, proven): C = A@B + bias, 128x128x8 tiles, fp32.
// ---------------------------------------------------------------------------
__global__ __launch_bounds__(256) void sgemm_bias_kernel(
    const float* __restrict__ A, const float* __restrict__ B,
    const float* __restrict__ bias, float* __restrict__ C,
    int M, int N, int K)
{
    __shared__ float As[8][128];
    __shared__ float Bs[8][128];

    const int tid = threadIdx.x;
    const int tx = tid & 15;
    const int ty = tid >> 4;
    const int rowBase = blockIdx.y * 128;
    const int colBase = blockIdx.x * 128;

    float acc[8][8];
#pragma unroll
    for (int i = 0; i < 8; i++)
#pragma unroll
        for (int j = 0; j < 8; j++) acc[i][j] = 0.f;

    const int aRow = tid >> 1;
    const int aCol = (tid & 1) * 4;
    const int bRow = tid >> 5;
    const int bCol = (tid & 31) * 4;

    const float* Ap = A + (size_t)(rowBase + aRow) * K + aCol;
    const float* Bp = B + (size_t)bRow * N + colBase + bCol;

    for (int k0 = 0; k0 < K; k0 += 8) {
        float4 av = *(const float4*)(Ap + k0);
        float4 bv = *(const float4*)(Bp + (size_t)k0 * N);
        As[aCol + 0][aRow] = av.x;
        As[aCol + 1][aRow] = av.y;
        As[aCol + 2][aRow] = av.z;
        As[aCol + 3][aRow] = av.w;
        *(float4*)&Bs[bRow][bCol] = bv;
        __syncthreads();
#pragma unroll
        for (int kk = 0; kk < 8; kk++) {
            float a[8], b[8];
            *(float4*)&a[0] = *(const float4*)&As[kk][ty * 4];
            *(float4*)&a[4] = *(const float4*)&As[kk][ty * 4 + 64];
            *(float4*)&b[0] = *(const float4*)&Bs[kk][tx * 4];
            *(float4*)&b[4] = *(const float4*)&Bs[kk][tx * 4 + 64];
#pragma unroll
            for (int i = 0; i < 8; i++)
#pragma unroll
                for (int j = 0; j < 8; j++)
                    acc[i][j] = fmaf(a[i], b[j], acc[i][j]);
        }
        __syncthreads();
    }

#pragma unroll
    for (int ii = 0; ii < 2; ii++) {
#pragma unroll
        for (int i = 0; i < 4; i++) {
            const int r = rowBase + ii * 64 + ty * 4 + i;
#pragma unroll
            for (int jj = 0; jj < 2; jj++) {
                const int c = colBase + jj * 64 + tx * 4;
                float4 bsv = *(const float4*)&bias[c];
                float4 o;
                o.x = acc[ii * 4 + i][jj * 4 + 0] + bsv.x;
                o.y = acc[ii * 4 + i][jj * 4 + 1] + bsv.y;
                o.z = acc[ii * 4 + i][jj * 4 + 2] + bsv.z;
                o.w = acc[ii * 4 + i][jj * 4 + 3] + bsv.w;
                *(float4*)&C[(size_t)r * N + c] = o;
            }
        }
    }
}

// ---------------------------------------------------------------------------
// MMA flash attention, bf16 split-3 (hi+lo), m16n8k16, fp32 accum.
// qkv row layout (stride 2304): [0,768)=K, [768,1536)=Q, [1536,2304)=V.
// Block tile 128q x 64tok. 8 warps; warp w owns q rows [16w,16w+16).
// smem tiles: Q/K/V/P in hi+lo bf16, row-major, k-dim contiguous, stride 72.
// ---------------------------------------------------------------------------
#define BSTR 72          // bf16 row stride (64 + 8 pad) -> 144B, LDSM conflict-free
#define OFF_QH 0
#define OFF_QL (OFF_QH + 128 * BSTR * 2)   // 18432
#define OFF_KH (OFF_QL + 128 * BSTR * 2)   // 36864
#define OFF_KL (OFF_KH + 64 * BSTR * 2)    // 46080
#define OFF_VH (OFF_KL + 64 * BSTR * 2)    // 55296
#define OFF_VL (OFF_VH + 64 * BSTR * 2)    // 64512
#define OFF_PH (OFF_VL + 64 * BSTR * 2)    // 73728
#define OFF_PL (OFF_PH + 128 * BSTR * 2)   // 92160
#define ATTN_SMEM (OFF_PL + 128 * BSTR * 2)  // 110592

__device__ __forceinline__ void ldsm_x4(uint32_t* r, uint32_t addr) {
    asm volatile("ldmatrix.sync.aligned.m8n8.x4.shared.b16 {%0,%1,%2,%3}, [%4];"
                 : "=r"(r[0]), "=r"(r[1]), "=r"(r[2]), "=r"(r[3]) : "r"(addr));
}
__device__ __forceinline__ void ldsm_x4_t(uint32_t* r, uint32_t addr) {
    asm volatile("ldmatrix.sync.aligned.m8n8.x4.trans.shared.b16 {%0,%1,%2,%3}, [%4];"
                 : "=r"(r[0]), "=r"(r[1]), "=r"(r[2]), "=r"(r[3]) : "r"(addr));
}
__device__ __forceinline__ void mma16816(float* c, const uint32_t* a, const uint32_t* b) {
    asm volatile("mma.sync.aligned.m16n8k16.row.col.f32.bf16.bf16.f32 "
                 "{%0,%1,%2,%3}, {%4,%5,%6,%7}, {%8,%9}, {%0,%1,%2,%3};"
                 : "+f"(c[0]), "+f"(c[1]), "+f"(c[2]), "+f"(c[3])
                 : "r"(a[0]), "r"(a[1]), "r"(a[2]), "r"(a[3]), "r"(b[0]), "r"(b[1]));
}

// Split x into hi/lo bf16 pairs; returns packed (b<<16)|a for hi, residual packed for lo.
__device__ __forceinline__ void split2(float a, float b, uint32_t& hi, uint32_t& lo) {
    __nv_bfloat16 ha = __float2bfloat16(a);
    __nv_bfloat16 hb = __float2bfloat16(b);
    __nv_bfloat16 la = __float2bfloat16(a - __bfloat162float(ha));
    __nv_bfloat16 lb = __float2bfloat16(b - __bfloat162float(hb));
    hi = ((uint32_t)__bfloat16_as_ushort(hb) << 16) | __bfloat16_as_ushort(ha);
    lo = ((uint32_t)__bfloat16_as_ushort(lb) << 16) | __bfloat16_as_ushort(la);
}

__global__ __launch_bounds__(256, 2) void attn_mma_kernel(
    const float* __restrict__ qkv, float* __restrict__ att)
{
    extern __shared__ char smc[];
    const uint32_t sb = (uint32_t)__cvta_generic_to_shared(smc);

    const int tid = threadIdx.x;
    const int lane = tid & 31;
    const int w = tid >> 5;            // 0..7
    const int qb = blockIdx.x;
    const int b  = blockIdx.y / NH;
    const int h  = blockIdx.y % NH;
    const int q0 = qb * 128;

    const size_t rowstr = 3 * CED;     // 2304
    const float* qbase = qkv + (size_t)(b * TSEQ + q0) * rowstr + CED + h * 64;
    const float* kbase = qkv + (size_t)(b * TSEQ) * rowstr + h * 64;
    const float* vbase = qkv + (size_t)(b * TSEQ) * rowstr + 2 * CED + h * 64;

    // ---- Load Q tile [128 x 64], pre-scaled by 1/8, split into hi/lo bf16 ----
    for (int idx = tid; idx < 128 * 16; idx += 256) {
        const int r = idx >> 4;
        const int c4 = (idx & 15) * 4;
        float4 v = *(const float4*)(qbase + (size_t)r * rowstr + c4);
        v.x *= 0.125f; v.y *= 0.125f; v.z *= 0.125f; v.w *= 0.125f;
        uint32_t h0, l0, h1, l1;
        split2(v.x, v.y, h0, l0);
        split2(v.z, v.w, h1, l1);
        const int boff = (r * BSTR + c4) * 2;
        *(uint2*)(smc + OFF_QH + boff) = make_uint2(h0, h1);
        *(uint2*)(smc + OFF_QL + boff) = make_uint2(l0, l1);
    }

    // ---- Per-lane ldmatrix address components ----
    const int arow = (lane & 7) + ((lane >> 3) & 1) * 8;      // A-frag row 0..15
    const int acol = (lane >> 4) * 8;                          // A-frag k-half
    const int brow = (lane >> 4) * 8 + (lane & 7);             // K B-frag row 0..15
    const int bcol = ((lane >> 3) & 1) * 8;                    // K B-frag k-half
    const int vrow = ((lane >> 3) & 1) * 8 + (lane & 7);       // V trans row 0..15
    const int vcol = (lane >> 4) * 8;                          // V trans col-half

    const uint32_t aQ = sb + OFF_QH + ((w * 16 + arow) * BSTR + acol) * 2;
    const uint32_t aP = sb + OFF_PH + ((w * 16 + arow) * BSTR + acol) * 2;
    const uint32_t bK = sb + OFF_KH + (brow * BSTR + bcol) * 2;
    const uint32_t bV = sb + OFF_VH + (vrow * BSTR + vcol) * 2;
    const uint32_t DQL = OFF_QL - OFF_QH;
    const uint32_t DKL = OFF_KL - OFF_KH;
    const uint32_t DVL = OFF_VL - OFF_VH;
    const uint32_t DPL = OFF_PL - OFF_PH;

    // Rows owned by this thread (softmax / output)
    const int qg0 = q0 + w * 16 + (lane >> 2);   // global q of row r0
    const int qg1 = qg0 + 8;

    float o[8][4];
#pragma unroll
    for (int j = 0; j < 8; j++)
#pragma unroll
        for (int c = 0; c < 4; c++) o[j][c] = 0.f;
    float mx0 = -1e30f, mx1 = -1e30f, sl0 = 0.f, sl1 = 0.f;

    const int ntiles = 2 * qb + 2;
    for (int kt = 0; kt < ntiles; kt++) {
        __syncthreads();   // protect K/V smem reuse; also covers initial Q visibility
        const int krow0 = kt * 64;

        // ---- Load K,V tiles [64 x 64], split into hi/lo bf16 ----
        for (int idx = tid; idx < 64 * 16; idx += 256) {
            const int r = idx >> 4;
            const int c4 = (idx & 15) * 4;
            const int boff = (r * BSTR + c4) * 2;
            float4 kv = *(const float4*)(kbase + (size_t)(krow0 + r) * rowstr + c4);
            uint32_t h0, l0, h1, l1;
            split2(kv.x, kv.y, h0, l0);
            split2(kv.z, kv.w, h1, l1);
            *(uint2*)(smc + OFF_KH + boff) = make_uint2(h0, h1);
            *(uint2*)(smc + OFF_KL + boff) = make_uint2(l0, l1);
            float4 vv = *(const float4*)(vbase + (size_t)(krow0 + r) * rowstr + c4);
            split2(vv.x, vv.y, h0, l0);
            split2(vv.z, vv.w, h1, l1);
            *(uint2*)(smc + OFF_VH + boff) = make_uint2(h0, h1);
            *(uint2*)(smc + OFF_VL + boff) = make_uint2(l0, l1);
        }
        __syncthreads();

        // ---- S = Qs @ K^T  (split-3 bf16) ----
        float acc[8][4];
#pragma unroll
        for (int j = 0; j < 8; j++)
#pragma unroll
            for (int c = 0; c < 4; c++) acc[j][c] = 0.f;

#pragma unroll
        for (int k0 = 0; k0 < 64; k0 += 16) {
            uint32_t qh[4], ql[4];
            ldsm_x4(qh, aQ + k0 * 2);
            ldsm_x4(ql, aQ + DQL + k0 * 2);
#pragma unroll
            for (int jp = 0; jp < 4; jp++) {
                uint32_t kh[4], kl[4];
                const uint32_t ba = bK + (jp * 16 * BSTR + k0) * 2;
                ldsm_x4(kh, ba);
                ldsm_x4(kl, ba + DKL);
                mma16816(acc[2 * jp],     qh, &kh[0]);
                mma16816(acc[2 * jp + 1], qh, &kh[2]);
                mma16816(acc[2 * jp],     qh, &kl[0]);
                mma16816(acc[2 * jp + 1], qh, &kl[2]);
                mma16816(acc[2 * jp],     ql, &kh[0]);
                mma16816(acc[2 * jp + 1], ql, &kh[2]);
            }
        }

        // ---- Causal mask (only diagonal tiles) ----
        if (kt >= 2 * qb) {
            const int tokc = krow0 + 2 * (lane & 3);
#pragma unroll
            for (int j = 0; j < 8; j++) {
                const int t0 = tokc + 8 * j;
                if (t0     > qg0) acc[j][0] = -1e30f;
                if (t0 + 1 > qg0) acc[j][1] = -1e30f;
                if (t0     > qg1) acc[j][2] = -1e30f;
                if (t0 + 1 > qg1) acc[j][3] = -1e30f;
            }
        }

        // ---- Online softmax (rows r0, r1; reduce over 4-lane groups) ----
        float rm0 = -1e30f, rm1 = -1e30f;
#pragma unroll
        for (int j = 0; j < 8; j++) {
            rm0 = fmaxf(rm0, fmaxf(acc[j][0], acc[j][1]));
            rm1 = fmaxf(rm1, fmaxf(acc[j][2], acc[j][3]));
        }
        rm0 = fmaxf(rm0, __shfl_xor_sync(0xffffffffu, rm0, 1));
        rm0 = fmaxf(rm0, __shfl_xor_sync(0xffffffffu, rm0, 2));
        rm1 = fmaxf(rm1, __shfl_xor_sync(0xffffffffu, rm1, 1));
        rm1 = fmaxf(rm1, __shfl_xor_sync(0xffffffffu, rm1, 2));
        const float mn0 = fmaxf(mx0, rm0);
        const float mn1 = fmaxf(mx1, rm1);
        const float sc0 = __expf(mx0 - mn0);
        const float sc1 = __expf(mx1 - mn1);

        const int r0 = w * 16 + (lane >> 2);
        const int colb = 2 * (lane & 3);
        float rs0 = 0.f, rs1 = 0.f;
#pragma unroll
        for (int j = 0; j < 8; j++) {
            const float p0 = __expf(acc[j][0] - mn0);
            const float p1 = __expf(acc[j][1] - mn0);
            const float p2 = __expf(acc[j][2] - mn1);
            const float p3 = __expf(acc[j][3] - mn1);
            rs0 += p0 + p1;
            rs1 += p2 + p3;
            uint32_t hi, lo;
            const int cb = (8 * j + colb) * 2;
            split2(p0, p1, hi, lo);
            *(uint32_t*)(smc + OFF_PH + r0 * BSTR * 2 + cb) = hi;
            *(uint32_t*)(smc + OFF_PL + r0 * BSTR * 2 + cb) = lo;
            split2(p2, p3, hi, lo);
            *(uint32_t*)(smc + OFF_PH + (r0 + 8) * BSTR * 2 + cb) = hi;
            *(uint32_t*)(smc + OFF_PL + (r0 + 8) * BSTR * 2 + cb) = lo;
        }
        rs0 += __shfl_xor_sync(0xffffffffu, rs0, 1);
        rs0 += __shfl_xor_sync(0xffffffffu, rs0, 2);
        rs1 += __shfl_xor_sync(0xffffffffu, rs1, 1);
        rs1 += __shfl_xor_sync(0xffffffffu, rs1, 2);
        sl0 = sl0 * sc0 + rs0;
        sl1 = sl1 * sc1 + rs1;
        mx0 = mn0;
        mx1 = mn1;
#pragma unroll
        for (int j = 0; j < 8; j++) {
            o[j][0] *= sc0; o[j][1] *= sc0;
            o[j][2] *= sc1; o[j][3] *= sc1;
        }
        __syncwarp();   // P smem (per-warp rows) visible to own warp's ldmatrix

        // ---- O += P @ V  (split-3 bf16, V via ldmatrix.trans) ----
#pragma unroll
        for (int k0 = 0; k0 < 64; k0 += 16) {
            uint32_t ph[4], pl[4];
            ldsm_x4(ph, aP + k0 * 2);
            ldsm_x4(pl, aP + DPL + k0 * 2);
#pragma unroll
            for (int jp = 0; jp < 4; jp++) {
                uint32_t vh[4], vl[4];
                const uint32_t ba = bV + (k0 * BSTR + jp * 16) * 2;
                ldsm_x4_t(vh, ba);
                ldsm_x4_t(vl, ba + DVL);
                mma16816(o[2 * jp],     ph, &vh[0]);
                mma16816(o[2 * jp + 1], ph, &vh[2]);
                mma16816(o[2 * jp],     ph, &vl[0]);
                mma16816(o[2 * jp + 1], ph, &vl[2]);
                mma16816(o[2 * jp],     pl, &vh[0]);
                mma16816(o[2 * jp + 1], pl, &vh[2]);
            }
        }
    }

    // ---- Normalize and write out [B,T,C] ----
    const float inv0 = 1.0f / sl0;
    const float inv1 = 1.0f / sl1;
    float* out0 = att + (size_t)(b * TSEQ + qg0) * CED + h * 64 + 2 * (lane & 3);
    float* out1 = att + (size_t)(b * TSEQ + qg1) * CED + h * 64 + 2 * (lane & 3);
#pragma unroll
    for (int j = 0; j < 8; j++) {
        float2 v0 = make_float2(o[j][0] * inv0, o[j][1] * inv0);
        float2 v1 = make_float2(o[j][2] * inv1, o[j][3] * inv1);
        *(float2*)(out0 + 8 * j) = v0;
        *(float2*)(out1 + 8 * j) = v1;
    }
}

// ---------------------------------------------------------------------------

extern "C" void kernel_launch(void* const* d_in, const int* in_sizes, int n_in,
                              void* d_out, int out_size)
{
    (void)in_sizes; (void)n_in; (void)out_size;
    const float* x      = (const float*)d_in[0];
    const float* W_attn = (const float*)d_in[1];
    const float* b_attn = (const float*)d_in[2];
    const float* W_proj = (const float*)d_in[3];
    const float* b_proj = (const float*)d_in[4];
    float* out = (float*)d_out;

    float* qkv = nullptr;
    float* attv = nullptr;
    cudaGetSymbolAddress((void**)&qkv, g_qkv);
    cudaGetSymbolAddress((void**)&attv, g_att);

    const int M = BATCH * TSEQ;   // 8192
    cudaFuncSetAttribute(attn_mma_kernel, cudaFuncAttributeMaxDynamicSharedMemorySize,
                         ATTN_SMEM);

    // 1) qkv = x @ W_attn + b_attn          [8192, 2304]
    sgemm_bias_kernel<<<dim3(3 * CED / 128, M / 128), 256>>>(
        x, W_attn, b_attn, qkv, M, 3 * CED, CED);

    // 2) causal flash attention (bf16 split-3 MMA)
    attn_mma_kernel<<<dim3(TSEQ / 128, BATCH * NH), 256, ATTN_SMEM>>>(qkv, attv);

    // 3) out = att @ W_proj + b_proj         [8192, 768]
    sgemm_bias_kernel<<<dim3(CED / 128, M / 128), 256>>>(
        attv, W_proj, b_proj, out, M, CED, CED);
}

// round 4
// speedup vs baseline: 2.4892x; 1.4072x over previous
#include <cuda_runtime.h>
#include <cuda_bf16.h>
#include <cstdint>

#define NH   12
#define TSEQ 4096
#define BATCH 2
#define CED  768
#define MTOT (BATCH * TSEQ)   // 8192

// ---------------- scratch (no cudaMalloc allowed) ----------------
__device__ float g_qkv[(size_t)MTOT * 3 * CED];                 // fp32 qkv
__device__ __nv_bfloat16 g_xh[(size_t)MTOT * CED];
__device__ __nv_bfloat16 g_xl[(size_t)MTOT * CED];
__device__ __nv_bfloat16 g_wah[(size_t)CED * 3 * CED];
__device__ __nv_bfloat16 g_wal[(size_t)CED * 3 * CED];
__device__ __nv_bfloat16 g_wph[(size_t)CED * CED];
__device__ __nv_bfloat16 g_wpl[(size_t)CED * CED];
__device__ __nv_bfloat16 g_atth[(size_t)MTOT * CED];
__device__ __nv_bfloat16 g_attl[(size_t)MTOT * CED];

// ---------------- common helpers ----------------
__device__ __forceinline__ void ldsm_x4(uint32_t* r, uint32_t addr) {
    asm volatile("ldmatrix.sync.aligned.m8n8.x4.shared.b16 {%0,%1,%2,%3}, [%4];"
                 : "=r"(r[0]), "=r"(r[1]), "=r"(r[2]), "=r"(r[3]) : "r"(addr));
}
__device__ __forceinline__ void ldsm_x4_t(uint32_t* r, uint32_t addr) {
    asm volatile("ldmatrix.sync.aligned.m8n8.x4.trans.shared.b16 {%0,%1,%2,%3}, [%4];"
                 : "=r"(r[0]), "=r"(r[1]), "=r"(r[2]), "=r"(r[3]) : "r"(addr));
}
__device__ __forceinline__ void mma16816(float* c, const uint32_t* a, const uint32_t* b) {
    asm volatile("mma.sync.aligned.m16n8k16.row.col.f32.bf16.bf16.f32 "
                 "{%0,%1,%2,%3}, {%4,%5,%6,%7}, {%8,%9}, {%0,%1,%2,%3};"
                 : "+f"(c[0]), "+f"(c[1]), "+f"(c[2]), "+f"(c[3])
                 : "r"(a[0]), "r"(a[1]), "r"(a[2]), "r"(a[3]), "r"(b[0]), "r"(b[1]));
}
__device__ __forceinline__ void split2(float a, float b, uint32_t& hi, uint32_t& lo) {
    __nv_bfloat16 ha = __float2bfloat16(a);
    __nv_bfloat16 hb = __float2bfloat16(b);
    __nv_bfloat16 la = __float2bfloat16(a - __bfloat162float(ha));
    __nv_bfloat16 lb = __float2bfloat16(b - __bfloat162float(hb));
    hi = ((uint32_t)__bfloat16_as_ushort(hb) << 16) | __bfloat16_as_ushort(ha);
    lo = ((uint32_t)__bfloat16_as_ushort(lb) << 16) | __bfloat16_as_ushort(la);
}
__device__ __forceinline__ void cpa16(uint32_t dst, const void* src) {
    asm volatile("cp.async.cg.shared.global [%0], [%1], 16;" :: "r"(dst), "l"(src));
}
#define CP_COMMIT asm volatile("cp.async.commit_group;")
#define CP_WAIT0  asm volatile("cp.async.wait_group 0;")

// ---------------- split prep kernel ----------------
__global__ __launch_bounds__(256) void split_kernel(
    const float* __restrict__ in, __nv_bfloat16* __restrict__ hi,
    __nv_bfloat16* __restrict__ lo, int n4)
{
    int idx = blockIdx.x * 256 + threadIdx.x;
    if (idx >= n4) return;
    float4 v = *(const float4*)(in + (size_t)idx * 4);
    uint32_t h0, l0, h1, l1;
    split2(v.x, v.y, h0, l0);
    split2(v.z, v.w, h1, l1);
    *(uint2*)(hi + (size_t)idx * 4) = make_uint2(h0, h1);
    *(uint2*)(lo + (size_t)idx * 4) = make_uint2(l0, l1);
}

// ---------------------------------------------------------------------------
// bf16 split-3 MMA GEMM: C[M,N] = A@B + bias, A/B pre-split hi/lo bf16.
// Tiles 128x128xk32, 8 warps (2m x 4n, warp 64x32), cp.async double buffer.
// M%128==0, N%128==0, K%32==0.
// ---------------------------------------------------------------------------
#define GSTRA 40     // A smem row stride (32 k + 8 pad) bf16
#define GSTRB 136    // B smem row stride (128 n + 8 pad) bf16
#define SA_BYTES (128 * GSTRA * 2)                 // 10240
#define SB_BYTES (32 * GSTRB * 2)                  // 8704
#define ST_AH 0
#define ST_AL SA_BYTES
#define ST_BH (2 * SA_BYTES)
#define ST_BL (2 * SA_BYTES + SB_BYTES)
#define STAGE_BYTES (2 * SA_BYTES + 2 * SB_BYTES)  // 37888
#define GEMM_SMEM (2 * STAGE_BYTES)                // 75776

__global__ __launch_bounds__(256) void gemm_mma_kernel(
    const __nv_bfloat16* __restrict__ Ah, const __nv_bfloat16* __restrict__ Al,
    const __nv_bfloat16* __restrict__ Bh, const __nv_bfloat16* __restrict__ Bl,
    const float* __restrict__ bias, float* __restrict__ C,
    int M, int N, int K)
{
    extern __shared__ char smc[];
    const uint32_t sb = (uint32_t)__cvta_generic_to_shared(smc);

    const int tid = threadIdx.x;
    const int lane = tid & 31;
    const int w = tid >> 5;
    const int rowBase = blockIdx.y * 128;
    const int colBase = blockIdx.x * 128;
    const int wm = (w & 1) * 64;        // warp m offset
    const int wn = (w >> 1) * 32;       // warp n offset

    // cp.async chunk coords (512 16B-chunks per array per stage, 2 per thread)
    const int ar0 = tid >> 2,  ac0 = (tid & 3) * 8;          // A chunk 0
    const int ar1 = (tid + 256) >> 2, ac1 = ((tid + 256) & 3) * 8;
    const int br0 = tid >> 4,  bc0 = (tid & 15) * 8;         // B chunk 0
    const int br1 = (tid + 256) >> 4, bc1 = ((tid + 256) & 15) * 8;

    const __nv_bfloat16* Ah0 = Ah + (size_t)(rowBase + ar0) * K + ac0;
    const __nv_bfloat16* Ah1 = Ah + (size_t)(rowBase + ar1) * K + ac1;
    const __nv_bfloat16* Al0 = Al + (size_t)(rowBase + ar0) * K + ac0;
    const __nv_bfloat16* Al1 = Al + (size_t)(rowBase + ar1) * K + ac1;
    const __nv_bfloat16* Bh0 = Bh + (size_t)br0 * N + colBase + bc0;
    const __nv_bfloat16* Bh1 = Bh + (size_t)br1 * N + colBase + bc1;
    const __nv_bfloat16* Bl0 = Bl + (size_t)br0 * N + colBase + bc0;
    const __nv_bfloat16* Bl1 = Bl + (size_t)br1 * N + colBase + bc1;

    const uint32_t dA0 = sb + ar0 * (GSTRA * 2) + ac0 * 2;
    const uint32_t dA1 = sb + ar1 * (GSTRA * 2) + ac1 * 2;
    const uint32_t dB0 = sb + br0 * (GSTRB * 2) + bc0 * 2;
    const uint32_t dB1 = sb + br1 * (GSTRB * 2) + bc1 * 2;

    // ldmatrix lane addresses
    const int arow = (lane & 7) + ((lane >> 3) & 1) * 8;
    const int acol = (lane >> 4) * 8;
    const int vrow = ((lane >> 3) & 1) * 8 + (lane & 7);
    const int vcol = (lane >> 4) * 8;
    const uint32_t aAl = sb + ((wm + arow) * GSTRA + acol) * 2;   // + ST_AH/AL
    const uint32_t aBl = sb + (vrow * GSTRB + vcol) * 2;          // + ST_BH/BL

    float acc[4][4][4];
#pragma unroll
    for (int i = 0; i < 4; i++)
#pragma unroll
        for (int j = 0; j < 4; j++)
#pragma unroll
            for (int c = 0; c < 4; c++) acc[i][j][c] = 0.f;

    const int NS = K / 32;

    // issue stage 0
    {
        const uint32_t so = 0;
        cpa16(dA0 + so + ST_AH, Ah0); cpa16(dA1 + so + ST_AH, Ah1);
        cpa16(dA0 + so + ST_AL, Al0); cpa16(dA1 + so + ST_AL, Al1);
        cpa16(dB0 + so + ST_BH, Bh0); cpa16(dB1 + so + ST_BH, Bh1);
        cpa16(dB0 + so + ST_BL, Bl0); cpa16(dB1 + so + ST_BL, Bl1);
        CP_COMMIT;
    }

    for (int s = 0; s < NS; s++) {
        CP_WAIT0;
        __syncthreads();
        if (s + 1 < NS) {
            const int k0 = (s + 1) * 32;
            const uint32_t so = ((s + 1) & 1) * STAGE_BYTES;
            cpa16(dA0 + so + ST_AH, Ah0 + k0); cpa16(dA1 + so + ST_AH, Ah1 + k0);
            cpa16(dA0 + so + ST_AL, Al0 + k0); cpa16(dA1 + so + ST_AL, Al1 + k0);
            cpa16(dB0 + so + ST_BH, Bh0 + (size_t)k0 * N);
            cpa16(dB1 + so + ST_BH, Bh1 + (size_t)k0 * N);
            cpa16(dB0 + so + ST_BL, Bl0 + (size_t)k0 * N);
            cpa16(dB1 + so + ST_BL, Bl1 + (size_t)k0 * N);
            CP_COMMIT;
        }
        const uint32_t so = (s & 1) * STAGE_BYTES;

#pragma unroll
        for (int kk = 0; kk < 32; kk += 16) {
            uint32_t ah[4][4], al[4][4];
#pragma unroll
            for (int mt = 0; mt < 4; mt++) {
                const uint32_t ad = aAl + so + (mt * 16 * GSTRA + kk) * 2;
                ldsm_x4(ah[mt], ad + ST_AH);
                ldsm_x4(al[mt], ad + ST_AL);
            }
#pragma unroll
            for (int nt = 0; nt < 2; nt++) {
                uint32_t bh[4], bl[4];
                const uint32_t bd = aBl + so + (kk * GSTRB + wn + nt * 16) * 2;
                ldsm_x4_t(bh, bd + ST_BH);
                ldsm_x4_t(bl, bd + ST_BL);
#pragma unroll
                for (int mt = 0; mt < 4; mt++) {
                    float* a0 = acc[mt][nt * 2];
                    float* a1 = acc[mt][nt * 2 + 1];
                    mma16816(a0, ah[mt], &bh[0]);
                    mma16816(a1, ah[mt], &bh[2]);
                    mma16816(a0, ah[mt], &bl[0]);
                    mma16816(a1, ah[mt], &bl[2]);
                    mma16816(a0, al[mt], &bh[0]);
                    mma16816(a1, al[mt], &bh[2]);
                }
            }
        }
        __syncthreads();
    }

    // epilogue: bias + store fp32
#pragma unroll
    for (int mt = 0; mt < 4; mt++) {
        const int r0 = rowBase + wm + mt * 16 + (lane >> 2);
#pragma unroll
        for (int nt = 0; nt < 2; nt++) {
#pragma unroll
            for (int jn = 0; jn < 2; jn++) {
                const int c = colBase + wn + nt * 16 + jn * 8 + 2 * (lane & 3);
                const float b0 = bias[c];
                const float b1 = bias[c + 1];
                float* a = acc[mt][nt * 2 + jn];
                *(float2*)&C[(size_t)r0 * N + c] =
                    make_float2(a[0] + b0, a[1] + b1);
                *(float2*)&C[(size_t)(r0 + 8) * N + c] =
                    make_float2(a[2] + b0, a[3] + b1);
            }
        }
    }
}

// ---------------------------------------------------------------------------
// MMA flash attention (unchanged core), epilogue now writes split bf16.
// ---------------------------------------------------------------------------
#define BSTR 72
#define OFF_QH 0
#define OFF_QL (OFF_QH + 128 * BSTR * 2)
#define OFF_KH (OFF_QL + 128 * BSTR * 2)
#define OFF_KL (OFF_KH + 64 * BSTR * 2)
#define OFF_VH (OFF_KL + 64 * BSTR * 2)
#define OFF_VL (OFF_VH + 64 * BSTR * 2)
#define OFF_PH (OFF_VL + 64 * BSTR * 2)
#define OFF_PL (OFF_PH + 128 * BSTR * 2)
#define ATTN_SMEM (OFF_PL + 128 * BSTR * 2)

__global__ __launch_bounds__(256, 2) void attn_mma_kernel(
    const float* __restrict__ qkv,
    __nv_bfloat16* __restrict__ atth, __nv_bfloat16* __restrict__ attl)
{
    extern __shared__ char smc[];
    const uint32_t sb = (uint32_t)__cvta_generic_to_shared(smc);

    const int tid = threadIdx.x;
    const int lane = tid & 31;
    const int w = tid >> 5;
    const int qb = blockIdx.x;
    const int b  = blockIdx.y / NH;
    const int h  = blockIdx.y % NH;
    const int q0 = qb * 128;

    const size_t rowstr = 3 * CED;
    const float* qbase = qkv + (size_t)(b * TSEQ + q0) * rowstr + CED + h * 64;
    const float* kbase = qkv + (size_t)(b * TSEQ) * rowstr + h * 64;
    const float* vbase = qkv + (size_t)(b * TSEQ) * rowstr + 2 * CED + h * 64;

    for (int idx = tid; idx < 128 * 16; idx += 256) {
        const int r = idx >> 4;
        const int c4 = (idx & 15) * 4;
        float4 v = *(const float4*)(qbase + (size_t)r * rowstr + c4);
        v.x *= 0.125f; v.y *= 0.125f; v.z *= 0.125f; v.w *= 0.125f;
        uint32_t h0, l0, h1, l1;
        split2(v.x, v.y, h0, l0);
        split2(v.z, v.w, h1, l1);
        const int boff = (r * BSTR + c4) * 2;
        *(uint2*)(smc + OFF_QH + boff) = make_uint2(h0, h1);
        *(uint2*)(smc + OFF_QL + boff) = make_uint2(l0, l1);
    }

    const int arow = (lane & 7) + ((lane >> 3) & 1) * 8;
    const int acol = (lane >> 4) * 8;
    const int brow = (lane >> 4) * 8 + (lane & 7);
    const int bcol = ((lane >> 3) & 1) * 8;
    const int vrow = ((lane >> 3) & 1) * 8 + (lane & 7);
    const int vcol = (lane >> 4) * 8;

    const uint32_t aQ = sb + OFF_QH + ((w * 16 + arow) * BSTR + acol) * 2;
    const uint32_t aP = sb + OFF_PH + ((w * 16 + arow) * BSTR + acol) * 2;
    const uint32_t bK = sb + OFF_KH + (brow * BSTR + bcol) * 2;
    const uint32_t bV = sb + OFF_VH + (vrow * BSTR + vcol) * 2;
    const uint32_t DQL = OFF_QL - OFF_QH;
    const uint32_t DKL = OFF_KL - OFF_KH;
    const uint32_t DVL = OFF_VL - OFF_VH;
    const uint32_t DPL = OFF_PL - OFF_PH;

    const int qg0 = q0 + w * 16 + (lane >> 2);
    const int qg1 = qg0 + 8;

    float o[8][4];
#pragma unroll
    for (int j = 0; j < 8; j++)
#pragma unroll
        for (int c = 0; c < 4; c++) o[j][c] = 0.f;
    float mx0 = -1e30f, mx1 = -1e30f, sl0 = 0.f, sl1 = 0.f;

    const int ntiles = 2 * qb + 2;
    for (int kt = 0; kt < ntiles; kt++) {
        __syncthreads();
        const int krow0 = kt * 64;

        for (int idx = tid; idx < 64 * 16; idx += 256) {
            const int r = idx >> 4;
            const int c4 = (idx & 15) * 4;
            const int boff = (r * BSTR + c4) * 2;
            float4 kv = *(const float4*)(kbase + (size_t)(krow0 + r) * rowstr + c4);
            uint32_t h0, l0, h1, l1;
            split2(kv.x, kv.y, h0, l0);
            split2(kv.z, kv.w, h1, l1);
            *(uint2*)(smc + OFF_KH + boff) = make_uint2(h0, h1);
            *(uint2*)(smc + OFF_KL + boff) = make_uint2(l0, l1);
            float4 vv = *(const float4*)(vbase + (size_t)(krow0 + r) * rowstr + c4);
            split2(vv.x, vv.y, h0, l0);
            split2(vv.z, vv.w, h1, l1);
            *(uint2*)(smc + OFF_VH + boff) = make_uint2(h0, h1);
            *(uint2*)(smc + OFF_VL + boff) = make_uint2(l0, l1);
        }
        __syncthreads();

        float acc[8][4];
#pragma unroll
        for (int j = 0; j < 8; j++)
#pragma unroll
            for (int c = 0; c < 4; c++) acc[j][c] = 0.f;

#pragma unroll
        for (int k0 = 0; k0 < 64; k0 += 16) {
            uint32_t qh[4], ql[4];
            ldsm_x4(qh, aQ + k0 * 2);
            ldsm_x4(ql, aQ + DQL + k0 * 2);
#pragma unroll
            for (int jp = 0; jp < 4; jp++) {
                uint32_t kh[4], kl[4];
                const uint32_t ba = bK + (jp * 16 * BSTR + k0) * 2;
                ldsm_x4(kh, ba);
                ldsm_x4(kl, ba + DKL);
                mma16816(acc[2 * jp],     qh, &kh[0]);
                mma16816(acc[2 * jp + 1], qh, &kh[2]);
                mma16816(acc[2 * jp],     qh, &kl[0]);
                mma16816(acc[2 * jp + 1], qh, &kl[2]);
                mma16816(acc[2 * jp],     ql, &kh[0]);
                mma16816(acc[2 * jp + 1], ql, &kh[2]);
            }
        }

        if (kt >= 2 * qb) {
            const int tokc = krow0 + 2 * (lane & 3);
#pragma unroll
            for (int j = 0; j < 8; j++) {
                const int t0 = tokc + 8 * j;
                if (t0     > qg0) acc[j][0] = -1e30f;
                if (t0 + 1 > qg0) acc[j][1] = -1e30f;
                if (t0     > qg1) acc[j][2] = -1e30f;
                if (t0 + 1 > qg1) acc[j][3] = -1e30f;
            }
        }

        float rm0 = -1e30f, rm1 = -1e30f;
#pragma unroll
        for (int j = 0; j < 8; j++) {
            rm0 = fmaxf(rm0, fmaxf(acc[j][0], acc[j][1]));
            rm1 = fmaxf(rm1, fmaxf(acc[j][2], acc[j][3]));
        }
        rm0 = fmaxf(rm0, __shfl_xor_sync(0xffffffffu, rm0, 1));
        rm0 = fmaxf(rm0, __shfl_xor_sync(0xffffffffu, rm0, 2));
        rm1 = fmaxf(rm1, __shfl_xor_sync(0xffffffffu, rm1, 1));
        rm1 = fmaxf(rm1, __shfl_xor_sync(0xffffffffu, rm1, 2));
        const float mn0 = fmaxf(mx0, rm0);
        const float mn1 = fmaxf(mx1, rm1);
        const float sc0 = __expf(mx0 - mn0);
        const float sc1 = __expf(mx1 - mn1);

        const int r0 = w * 16 + (lane >> 2);
        const int colb = 2 * (lane & 3);
        float rs0 = 0.f, rs1 = 0.f;
#pragma unroll
        for (int j = 0; j < 8; j++) {
            const float p0 = __expf(acc[j][0] - mn0);
            const float p1 = __expf(acc[j][1] - mn0);
            const float p2 = __expf(acc[j][2] - mn1);
            const float p3 = __expf(acc[j][3] - mn1);
            rs0 += p0 + p1;
            rs1 += p2 + p3;
            uint32_t hi, lo;
            const int cb = (8 * j + colb) * 2;
            split2(p0, p1, hi, lo);
            *(uint32_t*)(smc + OFF_PH + r0 * BSTR * 2 + cb) = hi;
            *(uint32_t*)(smc + OFF_PL + r0 * BSTR * 2 + cb) = lo;
            split2(p2, p3, hi, lo);
            *(uint32_t*)(smc + OFF_PH + (r0 + 8) * BSTR * 2 + cb) = hi;
            *(uint32_t*)(smc + OFF_PL + (r0 + 8) * BSTR * 2 + cb) = lo;
        }
        rs0 += __shfl_xor_sync(0xffffffffu, rs0, 1);
        rs0 += __shfl_xor_sync(0xffffffffu, rs0, 2);
        rs1 += __shfl_xor_sync(0xffffffffu, rs1, 1);
        rs1 += __shfl_xor_sync(0xffffffffu, rs1, 2);
        sl0 = sl0 * sc0 + rs0;
        sl1 = sl1 * sc1 + rs1;
        mx0 = mn0;
        mx1 = mn1;
#pragma unroll
        for (int j = 0; j < 8; j++) {
            o[j][0] *= sc0; o[j][1] *= sc0;
            o[j][2] *= sc1; o[j][3] *= sc1;
        }
        __syncwarp();

#pragma unroll
        for (int k0 = 0; k0 < 64; k0 += 16) {
            uint32_t ph[4], pl[4];
            ldsm_x4(ph, aP + k0 * 2);
            ldsm_x4(pl, aP + DPL + k0 * 2);
#pragma unroll
            for (int jp = 0; jp < 4; jp++) {
                uint32_t vh[4], vl[4];
                const uint32_t ba = bV + (k0 * BSTR + jp * 16) * 2;
                ldsm_x4_t(vh, ba);
                ldsm_x4_t(vl, ba + DVL);
                mma16816(o[2 * jp],     ph, &vh[0]);
                mma16816(o[2 * jp + 1], ph, &vh[2]);
                mma16816(o[2 * jp],     ph, &vl[0]);
                mma16816(o[2 * jp + 1], ph, &vl[2]);
                mma16816(o[2 * jp],     pl, &vh[0]);
                mma16816(o[2 * jp + 1], pl, &vh[2]);
            }
        }
    }

    // ---- Normalize, split to bf16 hi/lo, write ----
    const float inv0 = 1.0f / sl0;
    const float inv1 = 1.0f / sl1;
    const size_t base0 = (size_t)(b * TSEQ + qg0) * CED + h * 64 + 2 * (lane & 3);
    const size_t base1 = (size_t)(b * TSEQ + qg1) * CED + h * 64 + 2 * (lane & 3);
#pragma unroll
    for (int j = 0; j < 8; j++) {
        uint32_t hi, lo;
        split2(o[j][0] * inv0, o[j][1] * inv0, hi, lo);
        *(uint32_t*)(atth + base0 + 8 * j) = hi;
        *(uint32_t*)(attl + base0 + 8 * j) = lo;
        split2(o[j][2] * inv1, o[j][3] * inv1, hi, lo);
        *(uint32_t*)(atth + base1 + 8 * j) = hi;
        *(uint32_t*)(attl + base1 + 8 * j) = lo;
    }
}

// ---------------------------------------------------------------------------

extern "C" void kernel_launch(void* const* d_in, const int* in_sizes, int n_in,
                              void* d_out, int out_size)
{
    (void)in_sizes; (void)n_in; (void)out_size;
    const float* x      = (const float*)d_in[0];
    const float* W_attn = (const float*)d_in[1];
    const float* b_attn = (const float*)d_in[2];
    const float* W_proj = (const float*)d_in[3];
    const float* b_proj = (const float*)d_in[4];
    float* out = (float*)d_out;

    float* qkv = nullptr;
    __nv_bfloat16 *xh, *xl, *wah, *wal, *wph, *wpl, *atth, *attl;
    cudaGetSymbolAddress((void**)&qkv, g_qkv);
    cudaGetSymbolAddress((void**)&xh, g_xh);
    cudaGetSymbolAddress((void**)&xl, g_xl);
    cudaGetSymbolAddress((void**)&wah, g_wah);
    cudaGetSymbolAddress((void**)&wal, g_wal);
    cudaGetSymbolAddress((void**)&wph, g_wph);
    cudaGetSymbolAddress((void**)&wpl, g_wpl);
    cudaGetSymbolAddress((void**)&atth, g_atth);
    cudaGetSymbolAddress((void**)&attl, g_attl);

    cudaFuncSetAttribute(attn_mma_kernel, cudaFuncAttributeMaxDynamicSharedMemorySize,
                         ATTN_SMEM);
    cudaFuncSetAttribute(gemm_mma_kernel, cudaFuncAttributeMaxDynamicSharedMemorySize,
                         GEMM_SMEM);

    // split inputs to bf16 hi/lo
    {
        int n4 = MTOT * CED / 4;
        split_kernel<<<(n4 + 255) / 256, 256>>>(x, xh, xl, n4);
        n4 = CED * 3 * CED / 4;
        split_kernel<<<(n4 + 255) / 256, 256>>>(W_attn, wah, wal, n4);
        n4 = CED * CED / 4;
        split_kernel<<<(n4 + 255) / 256, 256>>>(W_proj, wph, wpl, n4);
    }

    // 1) qkv = x @ W_attn + b_attn   [8192, 2304]
    gemm_mma_kernel<<<dim3(3 * CED / 128, MTOT / 128), 256, GEMM_SMEM>>>(
        xh, xl, wah, wal, b_attn, qkv, MTOT, 3 * CED, CED);

    // 2) causal flash attention -> att split bf16
    attn_mma_kernel<<<dim3(TSEQ / 128, BATCH * NH), 256, ATTN_SMEM>>>(qkv, atth, attl);

    // 3) out = att @ W_proj + b_proj [8192, 768]
    gemm_mma_kernel<<<dim3(CED / 128, MTOT / 128), 256, GEMM_SMEM>>>(
        atth, attl, wph, wpl, b_proj, out, MTOT, CED, CED);
}

// round 5
// speedup vs baseline: 2.5033x; 1.0057x over previous
#include <cuda_runtime.h>
#include <cuda_bf16.h>
#include <cstdint>

#define NH   12
#define TSEQ 4096
#define BATCH 2
#define CED  768
#define MTOT (BATCH * TSEQ)   // 8192

// ---------------- scratch (no cudaMalloc allowed) ----------------
__device__ __nv_bfloat16 g_qkvh[(size_t)MTOT * 3 * CED];
__device__ __nv_bfloat16 g_qkvl[(size_t)MTOT * 3 * CED];
__device__ __nv_bfloat16 g_xh[(size_t)MTOT * CED];
__device__ __nv_bfloat16 g_xl[(size_t)MTOT * CED];
__device__ __nv_bfloat16 g_wah[(size_t)CED * 3 * CED];
__device__ __nv_bfloat16 g_wal[(size_t)CED * 3 * CED];
__device__ __nv_bfloat16 g_wph[(size_t)CED * CED];
__device__ __nv_bfloat16 g_wpl[(size_t)CED * CED];
__device__ __nv_bfloat16 g_atth[(size_t)MTOT * CED];
__device__ __nv_bfloat16 g_attl[(size_t)MTOT * CED];

// ---------------- common helpers ----------------
__device__ __forceinline__ void ldsm_x4(uint32_t* r, uint32_t addr) {
    asm volatile("ldmatrix.sync.aligned.m8n8.x4.shared.b16 {%0,%1,%2,%3}, [%4];"
                 : "=r"(r[0]), "=r"(r[1]), "=r"(r[2]), "=r"(r[3]) : "r"(addr));
}
__device__ __forceinline__ void ldsm_x4_t(uint32_t* r, uint32_t addr) {
    asm volatile("ldmatrix.sync.aligned.m8n8.x4.trans.shared.b16 {%0,%1,%2,%3}, [%4];"
                 : "=r"(r[0]), "=r"(r[1]), "=r"(r[2]), "=r"(r[3]) : "r"(addr));
}
__device__ __forceinline__ void mma16816(float* c, const uint32_t* a, const uint32_t* b) {
    asm volatile("mma.sync.aligned.m16n8k16.row.col.f32.bf16.bf16.f32 "
                 "{%0,%1,%2,%3}, {%4,%5,%6,%7}, {%8,%9}, {%0,%1,%2,%3};"
                 : "+f"(c[0]), "+f"(c[1]), "+f"(c[2]), "+f"(c[3])
                 : "r"(a[0]), "r"(a[1]), "r"(a[2]), "r"(a[3]), "r"(b[0]), "r"(b[1]));
}
__device__ __forceinline__ void split2(float a, float b, uint32_t& hi, uint32_t& lo) {
    __nv_bfloat16 ha = __float2bfloat16(a);
    __nv_bfloat16 hb = __float2bfloat16(b);
    __nv_bfloat16 la = __float2bfloat16(a - __bfloat162float(ha));
    __nv_bfloat16 lb = __float2bfloat16(b - __bfloat162float(hb));
    hi = ((uint32_t)__bfloat16_as_ushort(hb) << 16) | __bfloat16_as_ushort(ha);
    lo = ((uint32_t)__bfloat16_as_ushort(lb) << 16) | __bfloat16_as_ushort(la);
}
__device__ __forceinline__ void cpa16(uint32_t dst, const void* src) {
    asm volatile("cp.async.cg.shared.global [%0], [%1], 16;" :: "r"(dst), "l"(src));
}
#define CP_COMMIT asm volatile("cp.async.commit_group;")
#define CP_WAIT0  asm volatile("cp.async.wait_group 0;")
#define CP_WAIT1  asm volatile("cp.async.wait_group 1;")

// ---------------- split prep kernel ----------------
__global__ __launch_bounds__(256) void split_kernel(
    const float* __restrict__ in, __nv_bfloat16* __restrict__ hi,
    __nv_bfloat16* __restrict__ lo, int n4)
{
    int idx = blockIdx.x * 256 + threadIdx.x;
    if (idx >= n4) return;
    float4 v = *(const float4*)(in + (size_t)idx * 4);
    uint32_t h0, l0, h1, l1;
    split2(v.x, v.y, h0, l0);
    split2(v.z, v.w, h1, l1);
    *(uint2*)(hi + (size_t)idx * 4) = make_uint2(h0, h1);
    *(uint2*)(lo + (size_t)idx * 4) = make_uint2(l0, l1);
}

// ---------------------------------------------------------------------------
// bf16 split-3 MMA GEMM: out = A@B + bias. Output either fp32 C, or split
// bf16 (Ch/Cl) when Ch != nullptr.
// ---------------------------------------------------------------------------
#define GSTRA 40
#define GSTRB 136
#define SA_BYTES (128 * GSTRA * 2)
#define SB_BYTES (32 * GSTRB * 2)
#define ST_AH 0
#define ST_AL SA_BYTES
#define ST_BH (2 * SA_BYTES)
#define ST_BL (2 * SA_BYTES + SB_BYTES)
#define STAGE_BYTES (2 * SA_BYTES + 2 * SB_BYTES)
#define GEMM_SMEM (2 * STAGE_BYTES)

__global__ __launch_bounds__(256) void gemm_mma_kernel(
    const __nv_bfloat16* __restrict__ Ah, const __nv_bfloat16* __restrict__ Al,
    const __nv_bfloat16* __restrict__ Bh, const __nv_bfloat16* __restrict__ Bl,
    const float* __restrict__ bias, float* __restrict__ C,
    __nv_bfloat16* __restrict__ Ch, __nv_bfloat16* __restrict__ Cl,
    int M, int N, int K)
{
    extern __shared__ char smc[];
    const uint32_t sb = (uint32_t)__cvta_generic_to_shared(smc);

    const int tid = threadIdx.x;
    const int lane = tid & 31;
    const int w = tid >> 5;
    const int rowBase = blockIdx.y * 128;
    const int colBase = blockIdx.x * 128;
    const int wm = (w & 1) * 64;
    const int wn = (w >> 1) * 32;

    const int ar0 = tid >> 2,  ac0 = (tid & 3) * 8;
    const int ar1 = (tid + 256) >> 2, ac1 = ((tid + 256) & 3) * 8;
    const int br0 = tid >> 4,  bc0 = (tid & 15) * 8;
    const int br1 = (tid + 256) >> 4, bc1 = ((tid + 256) & 15) * 8;

    const __nv_bfloat16* Ah0 = Ah + (size_t)(rowBase + ar0) * K + ac0;
    const __nv_bfloat16* Ah1 = Ah + (size_t)(rowBase + ar1) * K + ac1;
    const __nv_bfloat16* Al0 = Al + (size_t)(rowBase + ar0) * K + ac0;
    const __nv_bfloat16* Al1 = Al + (size_t)(rowBase + ar1) * K + ac1;
    const __nv_bfloat16* Bh0 = Bh + (size_t)br0 * N + colBase + bc0;
    const __nv_bfloat16* Bh1 = Bh + (size_t)br1 * N + colBase + bc1;
    const __nv_bfloat16* Bl0 = Bl + (size_t)br0 * N + colBase + bc0;
    const __nv_bfloat16* Bl1 = Bl + (size_t)br1 * N + colBase + bc1;

    const uint32_t dA0 = sb + ar0 * (GSTRA * 2) + ac0 * 2;
    const uint32_t dA1 = sb + ar1 * (GSTRA * 2) + ac1 * 2;
    const uint32_t dB0 = sb + br0 * (GSTRB * 2) + bc0 * 2;
    const uint32_t dB1 = sb + br1 * (GSTRB * 2) + bc1 * 2;

    const int arow = (lane & 7) + ((lane >> 3) & 1) * 8;
    const int acol = (lane >> 4) * 8;
    const int vrow = ((lane >> 3) & 1) * 8 + (lane & 7);
    const int vcol = (lane >> 4) * 8;
    const uint32_t aAl = sb + ((wm + arow) * GSTRA + acol) * 2;
    const uint32_t aBl = sb + (vrow * GSTRB + vcol) * 2;

    float acc[4][4][4];
#pragma unroll
    for (int i = 0; i < 4; i++)
#pragma unroll
        for (int j = 0; j < 4; j++)
#pragma unroll
            for (int c = 0; c < 4; c++) acc[i][j][c] = 0.f;

    const int NS = K / 32;

    {
        cpa16(dA0 + ST_AH, Ah0); cpa16(dA1 + ST_AH, Ah1);
        cpa16(dA0 + ST_AL, Al0); cpa16(dA1 + ST_AL, Al1);
        cpa16(dB0 + ST_BH, Bh0); cpa16(dB1 + ST_BH, Bh1);
        cpa16(dB0 + ST_BL, Bl0); cpa16(dB1 + ST_BL, Bl1);
        CP_COMMIT;
    }

    for (int s = 0; s < NS; s++) {
        CP_WAIT0;
        __syncthreads();
        if (s + 1 < NS) {
            const int k0 = (s + 1) * 32;
            const uint32_t so = ((s + 1) & 1) * STAGE_BYTES;
            cpa16(dA0 + so + ST_AH, Ah0 + k0); cpa16(dA1 + so + ST_AH, Ah1 + k0);
            cpa16(dA0 + so + ST_AL, Al0 + k0); cpa16(dA1 + so + ST_AL, Al1 + k0);
            cpa16(dB0 + so + ST_BH, Bh0 + (size_t)k0 * N);
            cpa16(dB1 + so + ST_BH, Bh1 + (size_t)k0 * N);
            cpa16(dB0 + so + ST_BL, Bl0 + (size_t)k0 * N);
            cpa16(dB1 + so + ST_BL, Bl1 + (size_t)k0 * N);
            CP_COMMIT;
        }
        const uint32_t so = (s & 1) * STAGE_BYTES;

#pragma unroll
        for (int kk = 0; kk < 32; kk += 16) {
            uint32_t ah[4][4], al[4][4];
#pragma unroll
            for (int mt = 0; mt < 4; mt++) {
                const uint32_t ad = aAl + so + (mt * 16 * GSTRA + kk) * 2;
                ldsm_x4(ah[mt], ad + ST_AH);
                ldsm_x4(al[mt], ad + ST_AL);
            }
#pragma unroll
            for (int nt = 0; nt < 2; nt++) {
                uint32_t bh[4], bl[4];
                const uint32_t bd = aBl + so + (kk * GSTRB + wn + nt * 16) * 2;
                ldsm_x4_t(bh, bd + ST_BH);
                ldsm_x4_t(bl, bd + ST_BL);
#pragma unroll
                for (int mt = 0; mt < 4; mt++) {
                    float* a0 = acc[mt][nt * 2];
                    float* a1 = acc[mt][nt * 2 + 1];
                    mma16816(a0, ah[mt], &bh[0]);
                    mma16816(a1, ah[mt], &bh[2]);
                    mma16816(a0, ah[mt], &bl[0]);
                    mma16816(a1, ah[mt], &bl[2]);
                    mma16816(a0, al[mt], &bh[0]);
                    mma16816(a1, al[mt], &bh[2]);
                }
            }
        }
        __syncthreads();
    }

    // epilogue: bias + store (fp32 or split bf16)
#pragma unroll
    for (int mt = 0; mt < 4; mt++) {
        const int r0 = rowBase + wm + mt * 16 + (lane >> 2);
#pragma unroll
        for (int nt = 0; nt < 2; nt++) {
#pragma unroll
            for (int jn = 0; jn < 2; jn++) {
                const int c = colBase + wn + nt * 16 + jn * 8 + 2 * (lane & 3);
                const float b0 = bias[c];
                const float b1 = bias[c + 1];
                float* a = acc[mt][nt * 2 + jn];
                const float v00 = a[0] + b0, v01 = a[1] + b1;
                const float v10 = a[2] + b0, v11 = a[3] + b1;
                if (Ch) {
                    uint32_t hi, lo;
                    split2(v00, v01, hi, lo);
                    *(uint32_t*)(Ch + (size_t)r0 * N + c) = hi;
                    *(uint32_t*)(Cl + (size_t)r0 * N + c) = lo;
                    split2(v10, v11, hi, lo);
                    *(uint32_t*)(Ch + (size_t)(r0 + 8) * N + c) = hi;
                    *(uint32_t*)(Cl + (size_t)(r0 + 8) * N + c) = lo;
                } else {
                    *(float2*)&C[(size_t)r0 * N + c] = make_float2(v00, v01);
                    *(float2*)&C[(size_t)(r0 + 8) * N + c] = make_float2(v10, v11);
                }
            }
        }
    }
}

// ---------------------------------------------------------------------------
// MMA flash attention: consumes pre-split bf16 qkv via cp.async, K/V tiles
// double-buffered. Softmax scale 0.125 applied post-MMA (exact).
// Block tile 128q x 64tok, 8 warps (warp w owns q rows 16w..16w+15).
// ---------------------------------------------------------------------------
#define BSTR 72          // bf16 row stride, 144 B (16B-aligned, LDSM-friendly)
#define OFF_QH 0
#define OFF_QL (OFF_QH + 128 * BSTR * 2)   // 18432
#define OFF_PH (OFF_QL + 128 * BSTR * 2)   // 36864
#define OFF_PL (OFF_PH + 128 * BSTR * 2)   // 55296
#define OFF_KV0 (OFF_PL + 128 * BSTR * 2)  // 73728
#define KV_STAGE (4 * 64 * BSTR * 2)       // 36864 (KH,KL,VH,VL)
#define KV_KH 0
#define KV_KL (64 * BSTR * 2)              // 9216
#define KV_VH (2 * 64 * BSTR * 2)          // 18432
#define KV_VL (3 * 64 * BSTR * 2)          // 27648
#define ATTN_SMEM (OFF_KV0 + 2 * KV_STAGE) // 147456

__global__ __launch_bounds__(256) void attn_mma_kernel(
    const __nv_bfloat16* __restrict__ qkvh, const __nv_bfloat16* __restrict__ qkvl,
    __nv_bfloat16* __restrict__ atth, __nv_bfloat16* __restrict__ attl)
{
    extern __shared__ char smc[];
    const uint32_t sb = (uint32_t)__cvta_generic_to_shared(smc);

    const int tid = threadIdx.x;
    const int lane = tid & 31;
    const int w = tid >> 5;
    const int qb = blockIdx.x;
    const int b  = blockIdx.y / NH;
    const int h  = blockIdx.y % NH;
    const int q0 = qb * 128;

    const size_t rowstr = 3 * CED;   // 2304
    // column offsets within a qkv row (reference split order: k, q, v)
    const size_t colK = h * 64;
    const size_t colQ = CED + h * 64;
    const size_t colV = 2 * CED + h * 64;
    const size_t rowB = (size_t)b * TSEQ;

    // ---- Q tile loads (cp.async): 128 rows x 8 chunks per array ----
    for (int idx = tid; idx < 1024; idx += 256) {
        const int r = idx >> 3;
        const int e = (idx & 7) * 8;
        const size_t g = (rowB + q0 + r) * rowstr + colQ + e;
        const uint32_t d = sb + r * (BSTR * 2) + e * 2;
        cpa16(d + OFF_QH, qkvh + g);
        cpa16(d + OFF_QL, qkvl + g);
    }

    // ---- K/V per-thread chunk assignment ----
    const int kr = tid >> 2;            // 0..63
    const int ke = (tid & 3) * 8;       // elem 0..24 (chunk1 at +32)
    const size_t gK = (rowB + kr) * rowstr + colK + ke;
    const size_t gV = (rowB + kr) * rowstr + colV + ke;
    const uint32_t dKV = kr * (BSTR * 2) + ke * 2;

    // issue KV tile 0 into stage 0, same commit group as Q
    {
        const uint32_t s0 = sb + OFF_KV0;
        cpa16(s0 + KV_KH + dKV, qkvh + gK);
        cpa16(s0 + KV_KH + dKV + 64, qkvh + gK + 32);
        cpa16(s0 + KV_KL + dKV, qkvl + gK);
        cpa16(s0 + KV_KL + dKV + 64, qkvl + gK + 32);
        cpa16(s0 + KV_VH + dKV, qkvh + gV);
        cpa16(s0 + KV_VH + dKV + 64, qkvh + gV + 32);
        cpa16(s0 + KV_VL + dKV, qkvl + gV);
        cpa16(s0 + KV_VL + dKV + 64, qkvl + gV + 32);
        CP_COMMIT;
    }

    // ---- ldmatrix lane address components ----
    const int arow = (lane & 7) + ((lane >> 3) & 1) * 8;
    const int acol = (lane >> 4) * 8;
    const int brow = (lane >> 4) * 8 + (lane & 7);
    const int bcol = ((lane >> 3) & 1) * 8;
    const int vrow = ((lane >> 3) & 1) * 8 + (lane & 7);
    const int vcol = (lane >> 4) * 8;

    const uint32_t aQ = sb + OFF_QH + ((w * 16 + arow) * BSTR + acol) * 2;
    const uint32_t aP = sb + OFF_PH + ((w * 16 + arow) * BSTR + acol) * 2;
    const uint32_t lK = (brow * BSTR + bcol) * 2;       // + stage + KV_KH/KL
    const uint32_t lV = (vrow * BSTR + vcol) * 2;       // + stage + KV_VH/VL
    const uint32_t DQL = OFF_QL - OFF_QH;
    const uint32_t DPL = OFF_PL - OFF_PH;

    const int qg0 = q0 + w * 16 + (lane >> 2);
    const int qg1 = qg0 + 8;

    float o[8][4];
#pragma unroll
    for (int j = 0; j < 8; j++)
#pragma unroll
        for (int c = 0; c < 4; c++) o[j][c] = 0.f;
    float mx0 = -1e30f, mx1 = -1e30f, sl0 = 0.f, sl1 = 0.f;

    const int ntiles = 2 * qb + 2;
    for (int kt = 0; kt < ntiles; kt++) {
        // prefetch next KV tile into other stage
        if (kt + 1 < ntiles) {
            const size_t roff = (size_t)(kt + 1) * 64 * rowstr;
            const uint32_t sn = sb + OFF_KV0 + ((kt + 1) & 1) * KV_STAGE;
            cpa16(sn + KV_KH + dKV, qkvh + gK + roff);
            cpa16(sn + KV_KH + dKV + 64, qkvh + gK + roff + 32);
            cpa16(sn + KV_KL + dKV, qkvl + gK + roff);
            cpa16(sn + KV_KL + dKV + 64, qkvl + gK + roff + 32);
            cpa16(sn + KV_VH + dKV, qkvh + gV + roff);
            cpa16(sn + KV_VH + dKV + 64, qkvh + gV + roff + 32);
            cpa16(sn + KV_VL + dKV, qkvl + gV + roff);
            cpa16(sn + KV_VL + dKV + 64, qkvl + gV + roff + 32);
            CP_COMMIT;
            CP_WAIT1;
        } else {
            CP_WAIT0;
        }
        __syncthreads();   // KV tile kt visible to all warps

        const uint32_t stg = sb + OFF_KV0 + (kt & 1) * KV_STAGE;
        const int krow0 = kt * 64;

        // ---- S = Q @ K^T (split-3) ----
        float acc[8][4];
#pragma unroll
        for (int j = 0; j < 8; j++)
#pragma unroll
            for (int c = 0; c < 4; c++) acc[j][c] = 0.f;

#pragma unroll
        for (int k0 = 0; k0 < 64; k0 += 16) {
            uint32_t qh[4], ql[4];
            ldsm_x4(qh, aQ + k0 * 2);
            ldsm_x4(ql, aQ + DQL + k0 * 2);
#pragma unroll
            for (int jp = 0; jp < 4; jp++) {
                uint32_t kh[4], kl[4];
                const uint32_t ba = stg + lK + (jp * 16 * BSTR + k0) * 2;
                ldsm_x4(kh, ba + KV_KH);
                ldsm_x4(kl, ba + KV_KL);
                mma16816(acc[2 * jp],     qh, &kh[0]);
                mma16816(acc[2 * jp + 1], qh, &kh[2]);
                mma16816(acc[2 * jp],     qh, &kl[0]);
                mma16816(acc[2 * jp + 1], qh, &kl[2]);
                mma16816(acc[2 * jp],     ql, &kh[0]);
                mma16816(acc[2 * jp + 1], ql, &kh[2]);
            }
        }

        // scale (exact) then causal mask
#pragma unroll
        for (int j = 0; j < 8; j++)
#pragma unroll
            for (int c = 0; c < 4; c++) acc[j][c] *= 0.125f;

        if (kt >= 2 * qb) {
            const int tokc = krow0 + 2 * (lane & 3);
#pragma unroll
            for (int j = 0; j < 8; j++) {
                const int t0 = tokc + 8 * j;
                if (t0     > qg0) acc[j][0] = -1e30f;
                if (t0 + 1 > qg0) acc[j][1] = -1e30f;
                if (t0     > qg1) acc[j][2] = -1e30f;
                if (t0 + 1 > qg1) acc[j][3] = -1e30f;
            }
        }

        // ---- online softmax ----
        float rm0 = -1e30f, rm1 = -1e30f;
#pragma unroll
        for (int j = 0; j < 8; j++) {
            rm0 = fmaxf(rm0, fmaxf(acc[j][0], acc[j][1]));
            rm1 = fmaxf(rm1, fmaxf(acc[j][2], acc[j][3]));
        }
        rm0 = fmaxf(rm0, __shfl_xor_sync(0xffffffffu, rm0, 1));
        rm0 = fmaxf(rm0, __shfl_xor_sync(0xffffffffu, rm0, 2));
        rm1 = fmaxf(rm1, __shfl_xor_sync(0xffffffffu, rm1, 1));
        rm1 = fmaxf(rm1, __shfl_xor_sync(0xffffffffu, rm1, 2));
        const float mn0 = fmaxf(mx0, rm0);
        const float mn1 = fmaxf(mx1, rm1);
        const float sc0 = __expf(mx0 - mn0);
        const float sc1 = __expf(mx1 - mn1);

        const int r0 = w * 16 + (lane >> 2);
        const int colb = 2 * (lane & 3);
        float rs0 = 0.f, rs1 = 0.f;
#pragma unroll
        for (int j = 0; j < 8; j++) {
            const float p0 = __expf(acc[j][0] - mn0);
            const float p1 = __expf(acc[j][1] - mn0);
            const float p2 = __expf(acc[j][2] - mn1);
            const float p3 = __expf(acc[j][3] - mn1);
            rs0 += p0 + p1;
            rs1 += p2 + p3;
            uint32_t hi, lo;
            const int cb = (8 * j + colb) * 2;
            split2(p0, p1, hi, lo);
            *(uint32_t*)(smc + OFF_PH + r0 * BSTR * 2 + cb) = hi;
            *(uint32_t*)(smc + OFF_PL + r0 * BSTR * 2 + cb) = lo;
            split2(p2, p3, hi, lo);
            *(uint32_t*)(smc + OFF_PH + (r0 + 8) * BSTR * 2 + cb) = hi;
            *(uint32_t*)(smc + OFF_PL + (r0 + 8) * BSTR * 2 + cb) = lo;
        }
        rs0 += __shfl_xor_sync(0xffffffffu, rs0, 1);
        rs0 += __shfl_xor_sync(0xffffffffu, rs0, 2);
        rs1 += __shfl_xor_sync(0xffffffffu, rs1, 1);
        rs1 += __shfl_xor_sync(0xffffffffu, rs1, 2);
        sl0 = sl0 * sc0 + rs0;
        sl1 = sl1 * sc1 + rs1;
        mx0 = mn0;
        mx1 = mn1;
#pragma unroll
        for (int j = 0; j < 8; j++) {
            o[j][0] *= sc0; o[j][1] *= sc0;
            o[j][2] *= sc1; o[j][3] *= sc1;
        }
        __syncwarp();  // P rows are per-warp; visible to own warp's ldmatrix

        // ---- O += P @ V ----
#pragma unroll
        for (int k0 = 0; k0 < 64; k0 += 16) {
            uint32_t ph[4], pl[4];
            ldsm_x4(ph, aP + k0 * 2);
            ldsm_x4(pl, aP + DPL + k0 * 2);
#pragma unroll
            for (int jp = 0; jp < 4; jp++) {
                uint32_t vh[4], vl[4];
                const uint32_t ba = stg + lV + (k0 * BSTR + jp * 16) * 2;
                ldsm_x4_t(vh, ba + KV_VH);
                ldsm_x4_t(vl, ba + KV_VL);
                mma16816(o[2 * jp],     ph, &vh[0]);
                mma16816(o[2 * jp + 1], ph, &vh[2]);
                mma16816(o[2 * jp],     ph, &vl[0]);
                mma16816(o[2 * jp + 1], ph, &vl[2]);
                mma16816(o[2 * jp],     pl, &vh[0]);
                mma16816(o[2 * jp + 1], pl, &vh[2]);
            }
        }
        __syncthreads();  // stage (kt&1) free before iter kt+1 prefetches into it
    }

    // ---- normalize, split bf16, write ----
    const float inv0 = 1.0f / sl0;
    const float inv1 = 1.0f / sl1;
    const size_t base0 = (size_t)(b * TSEQ + qg0) * CED + h * 64 + 2 * (lane & 3);
    const size_t base1 = (size_t)(b * TSEQ + qg1) * CED + h * 64 + 2 * (lane & 3);
#pragma unroll
    for (int j = 0; j < 8; j++) {
        uint32_t hi, lo;
        split2(o[j][0] * inv0, o[j][1] * inv0, hi, lo);
        *(uint32_t*)(atth + base0 + 8 * j) = hi;
        *(uint32_t*)(attl + base0 + 8 * j) = lo;
        split2(o[j][2] * inv1, o[j][3] * inv1, hi, lo);
        *(uint32_t*)(atth + base1 + 8 * j) = hi;
        *(uint32_t*)(attl + base1 + 8 * j) = lo;
    }
}

// ---------------------------------------------------------------------------

extern "C" void kernel_launch(void* const* d_in, const int* in_sizes, int n_in,
                              void* d_out, int out_size)
{
    (void)in_sizes; (void)n_in; (void)out_size;
    const float* x      = (const float*)d_in[0];
    const float* W_attn = (const float*)d_in[1];
    const float* b_attn = (const float*)d_in[2];
    const float* W_proj = (const float*)d_in[3];
    const float* b_proj = (const float*)d_in[4];
    float* out = (float*)d_out;

    __nv_bfloat16 *qkvh, *qkvl, *xh, *xl, *wah, *wal, *wph, *wpl, *atth, *attl;
    cudaGetSymbolAddress((void**)&qkvh, g_qkvh);
    cudaGetSymbolAddress((void**)&qkvl, g_qkvl);
    cudaGetSymbolAddress((void**)&xh, g_xh);
    cudaGetSymbolAddress((void**)&xl, g_xl);
    cudaGetSymbolAddress((void**)&wah, g_wah);
    cudaGetSymbolAddress((void**)&wal, g_wal);
    cudaGetSymbolAddress((void**)&wph, g_wph);
    cudaGetSymbolAddress((void**)&wpl, g_wpl);
    cudaGetSymbolAddress((void**)&atth, g_atth);
    cudaGetSymbolAddress((void**)&attl, g_attl);

    cudaFuncSetAttribute(attn_mma_kernel, cudaFuncAttributeMaxDynamicSharedMemorySize,
                         ATTN_SMEM);
    cudaFuncSetAttribute(gemm_mma_kernel, cudaFuncAttributeMaxDynamicSharedMemorySize,
                         GEMM_SMEM);

    // split inputs to bf16 hi/lo
    {
        int n4 = MTOT * CED / 4;
        split_kernel<<<(n4 + 255) / 256, 256>>>(x, xh, xl, n4);
        n4 = CED * 3 * CED / 4;
        split_kernel<<<(n4 + 255) / 256, 256>>>(W_attn, wah, wal, n4);
        n4 = CED * CED / 4;
        split_kernel<<<(n4 + 255) / 256, 256>>>(W_proj, wph, wpl, n4);
    }

    // 1) qkv = x @ W_attn + b_attn   -> split bf16 output
    gemm_mma_kernel<<<dim3(3 * CED / 128, MTOT / 128), 256, GEMM_SMEM>>>(
        xh, xl, wah, wal, b_attn, nullptr, qkvh, qkvl, MTOT, 3 * CED, CED);

    // 2) causal flash attention -> att split bf16
    attn_mma_kernel<<<dim3(TSEQ / 128, BATCH * NH), 256, ATTN_SMEM>>>(
        qkvh, qkvl, atth, attl);

    // 3) out = att @ W_proj + b_proj  (fp32 output)
    gemm_mma_kernel<<<dim3(CED / 128, MTOT / 128), 256, GEMM_SMEM>>>(
        atth, attl, wph, wpl, b_proj, out, nullptr, nullptr, MTOT, CED, CED);
}